// round 4
// baseline (speedup 1.0000x reference)
#include <cuda_runtime.h>
#include <cstdint>

#define M_ATOMS 9216
#define A_ATOM  36
#define K_NB    24
#define D0      64
#define KC      3
#define HEADS   4
#define DHD     16
#define RBF_N   16
#define MAXB    4
#define KIN_DIM 99
#define OUTC    144   /* 64 (k) + 64 (v0) + 16 (v1) */
#define BIGF    1e9f
#define EPSF    1e-5f
#define FULLW   0xffffffffu
#define KNN_CAP 512

// ---------------- device scratch ----------------
__device__ int    g_nM;
__device__ int    g_midx[M_ATOMS];
__device__ float4 g_cxyz[M_ATOMS];          // xyz of masked atoms, w = atom index (bits)
__device__ float  g_WT[KIN_DIM * OUTC];     // [kk][144]
__device__ float  g_W2[21 * OUTC];          // We @ W_edge, [21][144]
__device__ float  g_b2[OUTC];               // be @ W_edge
__device__ float  g_P[M_ATOMS * OUTC];      // state @ W_state per atom
__device__ float  g_Qv[M_ATOMS * 64];       // q per atom
__device__ float  g_S[M_ATOMS * 64];        // node@Wself + b0 per atom

// ---------------- weight prep: WT, W2, b2 (one kernel, no cross-dep) ----------------
__device__ __forceinline__ float wedge_elem(int c, int d,
                                            const float* Wk, const float* Wv0,
                                            const float* Wv1) {
    int kk = 64 + c;
    if (d < 64)  return Wk [kk * 64 + d];
    if (d < 128) return Wv0[kk * 64 + (d - 64)];
    return Wv1[kk * 16 + (d - 128)];
}

__global__ void prep_kernel(const float* __restrict__ Wk, const float* __restrict__ Wv0,
                            const float* __restrict__ Wv1, const float* __restrict__ We,
                            const float* __restrict__ be) {
    int idx = blockIdx.x * blockDim.x + threadIdx.x;
    const int N_WT = KIN_DIM * OUTC;
    const int N_W2 = 21 * OUTC;
    if (idx < N_WT) {
        int kk = idx / OUTC, d = idx % OUTC;
        float v;
        if (d < 64)       v = Wk [kk * 64 + d];
        else if (d < 128) v = Wv0[kk * 64 + (d - 64)];
        else              v = Wv1[kk * 16 + (d - 128)];
        g_WT[idx] = v;
    } else if (idx < N_WT + N_W2) {
        int r = idx - N_WT;
        int t = r / OUTC, d = r % OUTC;
        float acc = 0.f;
        for (int c = 0; c < 32; ++c)
            acc = fmaf(We[t * 32 + c], wedge_elem(c, d, Wk, Wv0, Wv1), acc);
        g_W2[r] = acc;
    } else if (idx < N_WT + N_W2 + OUTC) {
        int d = idx - N_WT - N_W2;
        float acc = 0.f;
        for (int c = 0; c < 32; ++c)
            acc = fmaf(be[c], wedge_elem(c, d, Wk, Wv0, Wv1), acc);
        g_b2[d] = acc;
    }
}

// ---------------- mask + compaction (warp-shuffle scan, 4 barriers) ----------------
__global__ void compact_kernel(const int* __restrict__ seq,
                               const float* __restrict__ xyz,
                               const void* __restrict__ aamask) {
    __shared__ int s_wsum[32];
    __shared__ int s_nz_off4, s_f_ok, s_f_one;
    int tid = threadIdx.x, lane = tid & 31, wid = tid >> 5;
    if (tid == 0) { s_nz_off4 = 0; s_f_ok = 1; s_f_one = 0; }
    __syncthreads();

    const unsigned char* am8  = (const unsigned char*)aamask;
    const int*           am32 = (const int*)aamask;
    const float*         amf  = (const float*)aamask;
    const int NA = 21 * A_ATOM;

    for (int p = tid; p < NA; p += 1024)
        if ((p & 3) && am8[p]) atomicOr(&s_nz_off4, 1);
    for (int wi = tid; wi < NA / 4; wi += 1024) {
        float f = amf[wi];
        if (!(f == 0.0f || f == 1.0f)) atomicAnd(&s_f_ok, 0);
        if (f == 1.0f) atomicOr(&s_f_one, 1);
    }
    __syncthreads();
    int mode = (!s_nz_off4) ? 0 : ((s_f_ok && s_f_one) ? 2 : 1);

    int base = tid * 9;
    unsigned char f[9];
    int cnt = 0;
#pragma unroll
    for (int i = 0; i < 9; ++i) {
        int m = base + i;
        int l = m / A_ATOM, a = m % A_ATOM;
        int q = seq[l] * A_ATOM + a;
        int v;
        if (mode == 0)      v = am32[q];
        else if (mode == 1) v = (int)am8[q];
        else                v = (amf[q] != 0.0f);
        f[i] = (v != 0);
        cnt += f[i];
    }
    // warp inclusive scan
    int v = cnt;
#pragma unroll
    for (int off = 1; off < 32; off <<= 1) {
        int o = __shfl_up_sync(FULLW, v, off);
        if (lane >= off) v += o;
    }
    if (lane == 31) s_wsum[wid] = v;
    __syncthreads();
    if (wid == 0) {
        int t = s_wsum[lane];
#pragma unroll
        for (int off = 1; off < 32; off <<= 1) {
            int o = __shfl_up_sync(FULLW, t, off);
            if (lane >= off) t += o;
        }
        s_wsum[lane] = t;
    }
    __syncthreads();
    int pos = (wid ? s_wsum[wid - 1] : 0) + v - cnt;
#pragma unroll
    for (int i = 0; i < 9; ++i) {
        int m = base + i;
        if (f[i]) {
            g_midx[pos] = m;
            g_cxyz[pos] = make_float4(xyz[m * 3], xyz[m * 3 + 1], xyz[m * 3 + 2],
                                      __int_as_float(m));
            pos++;
        }
    }
    if (tid == 1023) g_nM = s_wsum[31];
}

// ---------------- per-atom precompute: out copy, P, q, self ----------------
__global__ void __launch_bounds__(144) pq_kernel(const float* __restrict__ state,
                                                 const float* __restrict__ grads,
                                                 const float* __restrict__ Wq,
                                                 const float* __restrict__ Wself,
                                                 const float* __restrict__ b0,
                                                 const float* __restrict__ xyz,
                                                 float* __restrict__ out) {
    // grid-stride init copy (all blocks participate)
    {
        const int total = M_ATOMS * 3 + M_ATOMS * D0;
        for (int i = blockIdx.x * 144 + threadIdx.x; i < total; i += gridDim.x * 144)
            out[i] = (i < M_ATOMS * 3) ? xyz[i] : state[i - M_ATOMS * 3];
    }
    int nM = g_nM;
    int base = blockIdx.x * 4;
    if (base >= nM) return;
    int tid = threadIdx.x;
    int nhere = min(4, nM - base);

    __shared__ float s_st[4][64];
    __shared__ float s_nr[4][3];
    for (int i = tid; i < 4 * 64; i += 144) {
        int a = i >> 6, k = i & 63;
        if (a < nhere) s_st[a][k] = state[g_midx[base + a] * 64 + k];
    }
    if (tid < 12) {
        int a = tid / 3, c = tid % 3;
        if (a < nhere) {
            int m = g_midx[base + a];
            float s = EPSF;
#pragma unroll
            for (int dd = 0; dd < 3; ++dd) {
                float v = grads[(c * M_ATOMS + m) * 3 + dd];
                s = fmaf(v, v, s);
            }
            s_nr[a][c] = sqrtf(s);
        }
    }
    __syncthreads();

    {
        float acc0 = 0.f, acc1 = 0.f, acc2 = 0.f, acc3 = 0.f;
        for (int k = 0; k < 64; ++k) {
            float wv = g_WT[k * OUTC + tid];
            acc0 = fmaf(s_st[0][k], wv, acc0);
            acc1 = fmaf(s_st[1][k], wv, acc1);
            acc2 = fmaf(s_st[2][k], wv, acc2);
            acc3 = fmaf(s_st[3][k], wv, acc3);
        }
        float accs[4] = {acc0, acc1, acc2, acc3};
        for (int a = 0; a < nhere; ++a)
            g_P[g_midx[base + a] * OUTC + tid] = accs[a];
    }
    if (tid < 64) {
        for (int a = 0; a < nhere; ++a) {
            float accq = 0.f, accs = b0[tid];
            for (int k = 0; k < 64; ++k) {
                float st = s_st[a][k];
                accq = fmaf(st, Wq[k * 64 + tid], accq);
                accs = fmaf(st, Wself[k * 64 + tid], accs);
            }
#pragma unroll
            for (int c = 0; c < KC; ++c)
                accq = fmaf(s_nr[a][c], Wq[(64 + c) * 64 + tid], accq);
            int m = g_midx[base + a];
            g_Qv[m * 64 + tid] = accq;
            g_S[m * 64 + tid]  = accs;
        }
    }
}

// ---------------- fused knn + attention: 2 atoms per block, 320 threads ----------------
__device__ __forceinline__ unsigned long long knn_pack(float d, int j) {
    return ((unsigned long long)__float_as_uint(d) << 32) | (unsigned)j;
}

__global__ void __launch_bounds__(320) fused_kernel(
    const int* __restrict__ seq, const float* __restrict__ xyz,
    const int* __restrict__ num_bonds, const float* __restrict__ state,
    const float* __restrict__ grads,
    const float* __restrict__ Wo0, float* __restrict__ out) {
    int nM = g_nM;
    if (blockIdx.x * 2 >= nM) return;
    int tid  = threadIdx.x;
    int slot = tid / 160;
    int st   = tid - slot * 160;
    int lane = st & 31;
    int qi   = blockIdx.x * 2 + slot;
    bool active = (qi < nM);
    int m = active ? g_midx[qi] : 0;

    __shared__ float s_kv[2][K_NB][OUTC + 1];   // knn scratch aliased into here
    __shared__ float s_q[2][64];
    __shared__ float s_rbf[2][K_NB][RBF_N];
    __shared__ float s_dirv[2][K_NB][3];
    __shared__ float s_l1j[2][K_NB][KC][3];
    __shared__ float s_inv[2][K_NB][KC];
    __shared__ int   s_bond[2][K_NB];
    __shared__ float s_logit[2][HEADS][K_NB];
    __shared__ float s_attn[2][HEADS][K_NB];
    __shared__ float s_o0[2][64];
    __shared__ float s_coef[2][K_NB][4];
    __shared__ float s_vm[2][K_NB][3];
    __shared__ int   s_idx[2][K_NB];
    __shared__ float s_ok[2][K_NB];

    // ---- phase A: knn (warp 0 of each slot) + q prefetch (other warps) ----
    if (active) {
        if (st < 32) {
            float* bd = &s_kv[slot][0][0];
            int*   bi = (int*)bd + KNN_CAP;
            float4 me = g_cxyz[qi];
            unsigned lmask = (1u << lane) - 1u;
            int target = min(K_NB, nM - 1);

            // sample: 3rd smallest of first 64 candidates -> threshold T
            float da = BIGF, db = BIGF;
            {
                int j = lane;
                if (j < nM && j != qi) {
                    float4 c = g_cxyz[j];
                    float dx = c.x - me.x, dy = c.y - me.y, dz = c.z - me.z;
                    da = dx * dx + dy * dy + dz * dz;
                }
                j = 32 + lane;
                if (j < nM && j != qi) {
                    float4 c = g_cxyz[j];
                    float dx = c.x - me.x, dy = c.y - me.y, dz = c.z - me.z;
                    db = dx * dx + dy * dy + dz * dz;
                }
            }
            float T;
            {
                float a = da, b = db, m3 = BIGF;
                for (int r = 0; r < 3; ++r) {
                    float v = fminf(a, b);
#pragma unroll
                    for (int off = 16; off; off >>= 1)
                        v = fminf(v, __shfl_xor_sync(FULLW, v, off));
                    m3 = v;
                    if (a == v) a = BIGF;
                    if (b == v) b = BIGF;
                }
                T = fminf(m3, BIGF * 0.4f);
            }

            int cnt = 0;
            bool valid = false;
            for (int attempt = 0; attempt < 12; ++attempt) {
                cnt = 0;
                for (int j0 = 0; j0 < nM; j0 += 32) {
                    int j = j0 + lane;
                    float d2 = BIGF;
                    if (j < nM && j != qi) {
                        float4 c = g_cxyz[j];
                        float dx = c.x - me.x, dy = c.y - me.y, dz = c.z - me.z;
                        d2 = dx * dx + dy * dy + dz * dz;
                    }
                    bool p = (d2 <= T);
                    unsigned ball = __ballot_sync(FULLW, p);
                    if (p) {
                        int pos = cnt + __popc(ball & lmask);
                        if (pos < KNN_CAP) { bd[pos] = d2; bi[pos] = j; }
                    }
                    cnt += __popc(ball);
                    if (cnt > KNN_CAP) break;
                }
                if (cnt >= target && cnt <= KNN_CAP) { valid = true; break; }
                if (cnt < target) T = fminf(T * 4.0f, BIGF * 0.4f);
                else              T = T * 0.35f;
            }
            __syncwarp();

            if (valid) {
                unsigned long long last = 0ull;
                for (int r = 0; r < K_NB; ++r) {
                    unsigned long long best = ~0ull;
                    for (int t = lane; t < cnt; t += 32) {
                        unsigned long long p = knn_pack(bd[t], bi[t]);
                        if (p >= last && p < best) best = p;
                    }
#pragma unroll
                    for (int off = 16; off; off >>= 1) {
                        unsigned long long o = __shfl_xor_sync(FULLW, best, off);
                        if (o < best) best = o;
                    }
                    if (lane == r) {
                        float d = __uint_as_float((unsigned)(best >> 32));
                        bool found = (best != ~0ull && d < BIGF * 0.5f);
                        s_idx[slot][r] = found ? g_midx[(unsigned)best & 0xffffffffu] : m;
                        s_ok[slot][r]  = found ? 1.f : 0.f;
                    }
                    last = best + 1ull;
                }
            } else {
                unsigned long long last = 0ull;
                for (int r = 0; r < K_NB; ++r) {
                    unsigned long long best = ~0ull;
                    for (int j = lane; j < nM; j += 32) {
                        float d2 = BIGF;
                        if (j != qi) {
                            float4 c = g_cxyz[j];
                            float dx = c.x - me.x, dy = c.y - me.y, dz = c.z - me.z;
                            d2 = dx * dx + dy * dy + dz * dz;
                        }
                        unsigned long long p = knn_pack(d2, j);
                        if (p >= last && p < best) best = p;
                    }
#pragma unroll
                    for (int off = 16; off; off >>= 1) {
                        unsigned long long o = __shfl_xor_sync(FULLW, best, off);
                        if (o < best) best = o;
                    }
                    if (lane == r) {
                        float d = __uint_as_float((unsigned)(best >> 32));
                        bool found = (best != ~0ull && d < BIGF * 0.5f);
                        s_idx[slot][r] = found ? g_midx[(unsigned)best & 0xffffffffu] : m;
                        s_ok[slot][r]  = found ? 1.f : 0.f;
                    }
                    last = best + 1ull;
                }
            }
        } else if (st < 96) {
            s_q[slot][st - 32] = g_Qv[m * 64 + (st - 32)];
        }
    }
    __syncthreads();

    // ---- phase B: per-edge geometry (24 threads per slot) ----
    if (active && st >= 32 && st < 32 + K_NB) {
        int e = st - 32;
        int j = s_idx[slot][e];
        float rx = xyz[j * 3]     - xyz[m * 3];
        float ry = xyz[j * 3 + 1] - xyz[m * 3 + 1];
        float rz = xyz[j * 3 + 2] - xyz[m * 3 + 2];
        float d2 = rx * rx + ry * ry + rz * rz;
        float dist = sqrtf(d2 + EPSF);
        float inv_d = 1.f / dist;
        float dvx = rx * inv_d, dvy = ry * inv_d, dvz = rz * inv_d;
        s_dirv[slot][e][0] = dvx; s_dirv[slot][e][1] = dvy; s_dirv[slot][e][2] = dvz;
#pragma unroll
        for (int c = 0; c < KC; ++c) {
            float lx = grads[(c * M_ATOMS + j) * 3 + 0];
            float ly = grads[(c * M_ATOMS + j) * 3 + 1];
            float lz = grads[(c * M_ATOMS + j) * 3 + 2];
            s_l1j[slot][e][c][0] = lx; s_l1j[slot][e][c][1] = ly; s_l1j[slot][e][c][2] = lz;
            s_inv[slot][e][c] = lx * dvx + ly * dvy + lz * dvz;
        }
        int ri = m / A_ATOM, ai = m % A_ATOM;
        int rj = j / A_ATOM, aj = j % A_ATOM;
        int b = 0;
        if (rj == ri) b = num_bonds[(seq[ri] * A_ATOM + ai) * A_ATOM + aj];
        s_bond[slot][e] = min(max(b, 0), MAXB);
#pragma unroll
        for (int t = 0; t < RBF_N; ++t) {
            float r = dist - 0.4f * (float)t;
            s_rbf[slot][e][t] = __expf(-2.f * r * r);
        }
    }
    __syncthreads();

    // ---- phase C: kv[e][d] = P[j][d] + b2 + rbf@W2 + W2[16+bond] + inv@Winv ----
    if (active && st < OUTC) {
        int d = st;
        float w2r[RBF_N];
#pragma unroll
        for (int t = 0; t < RBF_N; ++t) w2r[t] = g_W2[t * OUTC + d];
        float wb0 = g_W2[16 * OUTC + d];
        float wb1 = g_W2[17 * OUTC + d];
        float wb2 = g_W2[18 * OUTC + d];
        float wb3 = g_W2[19 * OUTC + d];
        float wb4 = g_W2[20 * OUTC + d];
        float wi0 = g_WT[96 * OUTC + d];
        float wi1 = g_WT[97 * OUTC + d];
        float wi2 = g_WT[98 * OUTC + d];
        float b2  = g_b2[d];
#pragma unroll 8
        for (int e = 0; e < K_NB; ++e) {
            int j = s_idx[slot][e];
            float acc = b2 + g_P[j * OUTC + d];
#pragma unroll
            for (int t = 0; t < RBF_N; ++t)
                acc = fmaf(s_rbf[slot][e][t], w2r[t], acc);
            int b = s_bond[slot][e];
            float wb = wb0;
            if (b == 1) wb = wb1;
            else if (b == 2) wb = wb2;
            else if (b == 3) wb = wb3;
            else if (b == 4) wb = wb4;
            acc += wb;
            acc = fmaf(s_inv[slot][e][0], wi0, acc);
            acc = fmaf(s_inv[slot][e][1], wi1, acc);
            acc = fmaf(s_inv[slot][e][2], wi2, acc);
            s_kv[slot][e][d] = acc;
        }
    }
    __syncthreads();

    // ---- phase D: logits ----
    if (active && st < HEADS * K_NB) {
        int h = st / K_NB, e = st % K_NB;
        float acc = 0.f;
#pragma unroll
        for (int dh = 0; dh < DHD; ++dh)
            acc = fmaf(s_q[slot][h * DHD + dh], s_kv[slot][e][h * DHD + dh], acc);
        s_logit[slot][h][e] = (s_ok[slot][e] > 0.f) ? acc * 0.25f : -1e9f;
    }
    __syncthreads();

    // ---- phase E: softmax (warp h of each slot handles head h) ----
    if (active) {
        int w = st >> 5;
        if (w < HEADS) {
            float v = (lane < K_NB) ? s_logit[slot][w][lane] : -1e30f;
            float mx = v;
            for (int off = 16; off > 0; off >>= 1)
                mx = fmaxf(mx, __shfl_xor_sync(FULLW, mx, off));
            float ex = (lane < K_NB) ? __expf(v - mx) : 0.f;
            float sm = ex;
            for (int off = 16; off > 0; off >>= 1)
                sm += __shfl_xor_sync(FULLW, sm, off);
            if (lane < K_NB) s_attn[slot][w][lane] = ex / sm;
        }
    }
    __syncthreads();

    // ---- phase F: o0, coef ----
    if (active) {
        if (st < 64) {
            int h = st >> 4;
            float acc = 0.f;
#pragma unroll
            for (int e = 0; e < K_NB; ++e)
                acc = fmaf(s_attn[slot][h][e], s_kv[slot][e][64 + st], acc);
            s_o0[slot][st] = acc;
        } else {
            int t = st - 64;
            int e = t % K_NB, c = t / K_NB;   // c < 4
            float acc = 0.f;
#pragma unroll
            for (int h = 0; h < HEADS; ++h)
                acc = fmaf(s_attn[slot][h][e], s_kv[slot][e][128 + h * 4 + c], acc);
            s_coef[slot][e][c] = acc;
        }
    }
    __syncthreads();

    // ---- phase G: out0 (state) + vmsg ----
    if (active) {
        if (st < 64) {
            float acc = g_S[m * 64 + st];          // node@Wself + b0 (precomputed)
            for (int i = 0; i < 64; ++i)
                acc = fmaf(s_o0[slot][i], Wo0[i * 64 + st], acc);
            out[M_ATOMS * 3 + m * 64 + st] = acc;
        } else if (st < 64 + K_NB) {
            int e = st - 64;
            float c0 = s_coef[slot][e][0];
#pragma unroll
            for (int dd = 0; dd < 3; ++dd) {
                float v = c0 * s_dirv[slot][e][dd];
#pragma unroll
                for (int c = 0; c < KC; ++c)
                    v = fmaf(s_coef[slot][e][c + 1], s_l1j[slot][e][c][dd], v);
                s_vm[slot][e][dd] = v;
            }
        }
    }
    __syncthreads();

    // ---- phase H: out1 (xyz shift) ----
    if (active && st < 3) {
        float acc = 0.f;
#pragma unroll
        for (int e = 0; e < K_NB; ++e) acc += s_vm[slot][e][st];
        out[m * 3 + st] = xyz[m * 3 + st] + acc * 0.01f;
    }
}

// ---------------- launch ----------------
extern "C" void kernel_launch(void* const* d_in, const int* in_sizes, int n_in,
                              void* d_out, int out_size) {
    const int*   seq       = (const int*)d_in[0];
    const float* xyz       = (const float*)d_in[1];
    const void*  aamask    = d_in[2];
    const int*   num_bonds = (const int*)d_in[3];
    const float* state     = (const float*)d_in[4];
    const float* grads     = (const float*)d_in[5];
    int w = 6;
    if (n_in >= 16 && in_sizes[6] == 1) w = 7;
    const float* We    = (const float*)d_in[w + 0];
    const float* be    = (const float*)d_in[w + 1];
    const float* Wq    = (const float*)d_in[w + 2];
    const float* Wk    = (const float*)d_in[w + 3];
    const float* Wv0   = (const float*)d_in[w + 4];
    const float* Wv1   = (const float*)d_in[w + 5];
    const float* Wo0   = (const float*)d_in[w + 6];
    const float* Wself = (const float*)d_in[w + 7];
    const float* b0    = (const float*)d_in[w + 8];
    float* out = (float*)d_out;

    const int prep_total = KIN_DIM * OUTC + 21 * OUTC + OUTC;
    prep_kernel<<<(prep_total + 255) / 256, 256>>>(Wk, Wv0, Wv1, We, be);
    compact_kernel<<<1, 1024>>>(seq, xyz, aamask);
    pq_kernel<<<(M_ATOMS + 3) / 4, 144>>>(state, grads, Wq, Wself, b0, xyz, out);
    fused_kernel<<<(M_ATOMS + 1) / 2, 320>>>(seq, xyz, num_bonds, state, grads,
                                             Wo0, out);
}

// round 5
// speedup vs baseline: 1.8421x; 1.8421x over previous
#include <cuda_runtime.h>
#include <cstdint>

#define M_ATOMS 9216
#define A_ATOM  36
#define K_NB    24
#define D0      64
#define KC      3
#define HEADS   4
#define DHD     16
#define RBF_N   16
#define MAXB    4
#define KIN_DIM 99
#define OUTC    144   /* 64 (k) + 64 (v0) + 16 (v1) */
#define BIGF    1e9f
#define EPSF    1e-5f
#define FULLW   0xffffffffu
#define KNN_CAP 512

// ---------------- device scratch ----------------
__device__ int    g_nM;
__device__ int    g_midx[M_ATOMS];
__device__ float4 g_cxyz[M_ATOMS];          // xyz of masked atoms, w = atom index (bits)
__device__ int    g_knn[M_ATOMS * K_NB];
__device__ float  g_WT[KIN_DIM * OUTC];     // [kk][144]
__device__ float  g_W2[21 * OUTC];          // We @ W_edge, [21][144]
__device__ float  g_b2[OUTC];               // be @ W_edge
__device__ float  g_P[M_ATOMS * OUTC];      // state @ W_state per atom
__device__ float  g_Qv[M_ATOMS * 64];       // q per atom
__device__ float  g_S[M_ATOMS * 64];        // node@Wself + b0 per atom

// ---------------- weight prep: WT, W2, b2 (one kernel) ----------------
__device__ __forceinline__ float wedge_elem(int c, int d,
                                            const float* Wk, const float* Wv0,
                                            const float* Wv1) {
    int kk = 64 + c;
    if (d < 64)  return Wk [kk * 64 + d];
    if (d < 128) return Wv0[kk * 64 + (d - 64)];
    return Wv1[kk * 16 + (d - 128)];
}

__global__ void prep_kernel(const float* __restrict__ Wk, const float* __restrict__ Wv0,
                            const float* __restrict__ Wv1, const float* __restrict__ We,
                            const float* __restrict__ be) {
    int idx = blockIdx.x * blockDim.x + threadIdx.x;
    const int N_WT = KIN_DIM * OUTC;
    const int N_W2 = 21 * OUTC;
    if (idx < N_WT) {
        int kk = idx / OUTC, d = idx % OUTC;
        float v;
        if (d < 64)       v = Wk [kk * 64 + d];
        else if (d < 128) v = Wv0[kk * 64 + (d - 64)];
        else              v = Wv1[kk * 16 + (d - 128)];
        g_WT[idx] = v;
    } else if (idx < N_WT + N_W2) {
        int r = idx - N_WT;
        int t = r / OUTC, d = r % OUTC;
        float acc = 0.f;
        for (int c = 0; c < 32; ++c)
            acc = fmaf(We[t * 32 + c], wedge_elem(c, d, Wk, Wv0, Wv1), acc);
        g_W2[r] = acc;
    } else if (idx < N_WT + N_W2 + OUTC) {
        int d = idx - N_WT - N_W2;
        float acc = 0.f;
        for (int c = 0; c < 32; ++c)
            acc = fmaf(be[c], wedge_elem(c, d, Wk, Wv0, Wv1), acc);
        g_b2[d] = acc;
    }
}

// ---------------- mask + compaction (warp-shuffle scan) ----------------
__global__ void compact_kernel(const int* __restrict__ seq,
                               const float* __restrict__ xyz,
                               const void* __restrict__ aamask) {
    __shared__ int s_wsum[32];
    __shared__ int s_nz_off4, s_f_ok, s_f_one;
    int tid = threadIdx.x, lane = tid & 31, wid = tid >> 5;
    if (tid == 0) { s_nz_off4 = 0; s_f_ok = 1; s_f_one = 0; }
    __syncthreads();

    const unsigned char* am8  = (const unsigned char*)aamask;
    const int*           am32 = (const int*)aamask;
    const float*         amf  = (const float*)aamask;
    const int NA = 21 * A_ATOM;

    for (int p = tid; p < NA; p += 1024)
        if ((p & 3) && am8[p]) atomicOr(&s_nz_off4, 1);
    for (int wi = tid; wi < NA / 4; wi += 1024) {
        float f = amf[wi];
        if (!(f == 0.0f || f == 1.0f)) atomicAnd(&s_f_ok, 0);
        if (f == 1.0f) atomicOr(&s_f_one, 1);
    }
    __syncthreads();
    int mode = (!s_nz_off4) ? 0 : ((s_f_ok && s_f_one) ? 2 : 1);

    int base = tid * 9;
    unsigned char f[9];
    int cnt = 0;
#pragma unroll
    for (int i = 0; i < 9; ++i) {
        int m = base + i;
        int l = m / A_ATOM, a = m % A_ATOM;
        int q = seq[l] * A_ATOM + a;
        int v;
        if (mode == 0)      v = am32[q];
        else if (mode == 1) v = (int)am8[q];
        else                v = (amf[q] != 0.0f);
        f[i] = (v != 0);
        cnt += f[i];
    }
    int v = cnt;
#pragma unroll
    for (int off = 1; off < 32; off <<= 1) {
        int o = __shfl_up_sync(FULLW, v, off);
        if (lane >= off) v += o;
    }
    if (lane == 31) s_wsum[wid] = v;
    __syncthreads();
    if (wid == 0) {
        int t = s_wsum[lane];
#pragma unroll
        for (int off = 1; off < 32; off <<= 1) {
            int o = __shfl_up_sync(FULLW, t, off);
            if (lane >= off) t += o;
        }
        s_wsum[lane] = t;
    }
    __syncthreads();
    int pos = (wid ? s_wsum[wid - 1] : 0) + v - cnt;
#pragma unroll
    for (int i = 0; i < 9; ++i) {
        int m = base + i;
        if (f[i]) {
            g_midx[pos] = m;
            g_cxyz[pos] = make_float4(xyz[m * 3], xyz[m * 3 + 1], xyz[m * 3 + 2],
                                      __int_as_float(m));
            pos++;
        }
    }
    if (tid == 1023) g_nM = s_wsum[31];
}

// ---------------- per-atom precompute: out copy, P, q, self ----------------
__global__ void __launch_bounds__(144) pq_kernel(const float* __restrict__ state,
                                                 const float* __restrict__ grads,
                                                 const float* __restrict__ Wq,
                                                 const float* __restrict__ Wself,
                                                 const float* __restrict__ b0,
                                                 const float* __restrict__ xyz,
                                                 float* __restrict__ out) {
    // grid-stride init copy (all blocks participate)
    {
        const int total = M_ATOMS * 3 + M_ATOMS * D0;
        for (int i = blockIdx.x * 144 + threadIdx.x; i < total; i += gridDim.x * 144)
            out[i] = (i < M_ATOMS * 3) ? xyz[i] : state[i - M_ATOMS * 3];
    }
    int nM = g_nM;
    int base = blockIdx.x * 4;
    if (base >= nM) return;
    int tid = threadIdx.x;
    int nhere = min(4, nM - base);

    __shared__ float s_st[4][64];
    __shared__ float s_nr[4][3];
    for (int i = tid; i < 4 * 64; i += 144) {
        int a = i >> 6, k = i & 63;
        if (a < nhere) s_st[a][k] = state[g_midx[base + a] * 64 + k];
    }
    if (tid < 12) {
        int a = tid / 3, c = tid % 3;
        if (a < nhere) {
            int m = g_midx[base + a];
            float s = EPSF;
#pragma unroll
            for (int dd = 0; dd < 3; ++dd) {
                float v = grads[(c * M_ATOMS + m) * 3 + dd];
                s = fmaf(v, v, s);
            }
            s_nr[a][c] = sqrtf(s);
        }
    }
    __syncthreads();

    {
        float acc0 = 0.f, acc1 = 0.f, acc2 = 0.f, acc3 = 0.f;
        for (int k = 0; k < 64; ++k) {
            float wv = g_WT[k * OUTC + tid];
            acc0 = fmaf(s_st[0][k], wv, acc0);
            acc1 = fmaf(s_st[1][k], wv, acc1);
            acc2 = fmaf(s_st[2][k], wv, acc2);
            acc3 = fmaf(s_st[3][k], wv, acc3);
        }
        float accs[4] = {acc0, acc1, acc2, acc3};
        for (int a = 0; a < nhere; ++a)
            g_P[g_midx[base + a] * OUTC + tid] = accs[a];
    }
    if (tid < 64) {
        for (int a = 0; a < nhere; ++a) {
            float accq = 0.f, accs = b0[tid];
            for (int k = 0; k < 64; ++k) {
                float st = s_st[a][k];
                accq = fmaf(st, Wq[k * 64 + tid], accq);
                accs = fmaf(st, Wself[k * 64 + tid], accs);
            }
#pragma unroll
            for (int c = 0; c < KC; ++c)
                accq = fmaf(s_nr[a][c], Wq[(64 + c) * 64 + tid], accq);
            int m = g_midx[base + a];
            g_Qv[m * 64 + tid] = accq;
            g_S[m * 64 + tid]  = accs;
        }
    }
}

// ---------------- exact top-24: threshold-collect + small select ----------------
__device__ __forceinline__ unsigned long long knn_pack(float d, int j) {
    return ((unsigned long long)__float_as_uint(d) << 32) | (unsigned)j;
}

__global__ void __launch_bounds__(128) knn_kernel(void) {
    __shared__ float s_bd[4][KNN_CAP];
    __shared__ int   s_bi[4][KNN_CAP];
    int w    = threadIdx.x >> 5;
    int lane = threadIdx.x & 31;
    int qi   = blockIdx.x * 4 + w;
    int nM   = g_nM;
    if (qi >= nM) return;
    int m = g_midx[qi];
    float4 me = g_cxyz[qi];
    unsigned lmask = (1u << lane) - 1u;
    int target = min(K_NB, nM - 1);

    // ---- sample: 3rd smallest of first 64 candidates ----
    float da = BIGF, db = BIGF;
    {
        int j = lane;
        if (j < nM && j != qi) {
            float4 c = g_cxyz[j];
            float dx = c.x - me.x, dy = c.y - me.y, dz = c.z - me.z;
            da = dx * dx + dy * dy + dz * dz;
        }
        j = 32 + lane;
        if (j < nM && j != qi) {
            float4 c = g_cxyz[j];
            float dx = c.x - me.x, dy = c.y - me.y, dz = c.z - me.z;
            db = dx * dx + dy * dy + dz * dz;
        }
    }
    float T;
    {
        float a = da, b = db, m3 = BIGF;
        for (int r = 0; r < 3; ++r) {
            float v = fminf(a, b);
#pragma unroll
            for (int off = 16; off; off >>= 1)
                v = fminf(v, __shfl_xor_sync(FULLW, v, off));
            m3 = v;
            if (a == v) a = BIGF;
            if (b == v) b = BIGF;
        }
        T = fminf(m3, BIGF * 0.4f);
    }

    int cnt = 0;
    bool valid = false;
    for (int attempt = 0; attempt < 12; ++attempt) {
        cnt = 0;
        for (int j0 = 0; j0 < nM; j0 += 32) {
            int j = j0 + lane;
            float d2 = BIGF;
            if (j < nM && j != qi) {
                float4 c = g_cxyz[j];
                float dx = c.x - me.x, dy = c.y - me.y, dz = c.z - me.z;
                d2 = dx * dx + dy * dy + dz * dz;
            }
            bool p = (d2 <= T);
            unsigned ball = __ballot_sync(FULLW, p);
            if (p) {
                int pos = cnt + __popc(ball & lmask);
                if (pos < KNN_CAP) { s_bd[w][pos] = d2; s_bi[w][pos] = j; }
            }
            cnt += __popc(ball);
            if (cnt > KNN_CAP) break;
        }
        if (cnt >= target && cnt <= KNN_CAP) { valid = true; break; }
        if (cnt < target) T = fminf(T * 4.0f, BIGF * 0.4f);
        else              T = T * 0.35f;
    }
    __syncwarp();

    if (valid) {
        unsigned long long last = 0ull;
        for (int r = 0; r < K_NB; ++r) {
            unsigned long long best = ~0ull;
            for (int t = lane; t < cnt; t += 32) {
                unsigned long long p = knn_pack(s_bd[w][t], s_bi[w][t]);
                if (p >= last && p < best) best = p;
            }
#pragma unroll
            for (int off = 16; off; off >>= 1) {
                unsigned long long o = __shfl_xor_sync(FULLW, best, off);
                if (o < best) best = o;
            }
            if (lane == r) {
                float d = __uint_as_float((unsigned)(best >> 32));
                g_knn[m * K_NB + r] =
                    (best != ~0ull && d < BIGF * 0.5f) ? g_midx[(unsigned)best & 0xffffffffu] : m;
            }
            last = best + 1ull;
        }
    } else {
        unsigned long long last = 0ull;
        for (int r = 0; r < K_NB; ++r) {
            unsigned long long best = ~0ull;
            for (int j = lane; j < nM; j += 32) {
                float d2 = BIGF;
                if (j != qi) {
                    float4 c = g_cxyz[j];
                    float dx = c.x - me.x, dy = c.y - me.y, dz = c.z - me.z;
                    d2 = dx * dx + dy * dy + dz * dz;
                }
                unsigned long long p = knn_pack(d2, j);
                if (p >= last && p < best) best = p;
            }
#pragma unroll
            for (int off = 16; off; off >>= 1) {
                unsigned long long o = __shfl_xor_sync(FULLW, best, off);
                if (o < best) best = o;
            }
            if (lane == r) {
                float d = __uint_as_float((unsigned)(best >> 32));
                g_knn[m * K_NB + r] =
                    (best != ~0ull && d < BIGF * 0.5f) ? g_midx[(unsigned)best & 0xffffffffu] : m;
            }
            last = best + 1ull;
        }
    }
}

// ---------------- per-atom edge attention (decomposed, 4 barriers) ----------------
__global__ void __launch_bounds__(160) attn_kernel(
    const int* __restrict__ seq, const float* __restrict__ xyz,
    const int* __restrict__ num_bonds, const float* __restrict__ grads,
    const float* __restrict__ Wo0, float* __restrict__ out) {
    if (blockIdx.x >= g_nM) return;
    int m = g_midx[blockIdx.x];
    int tid = threadIdx.x;
    int lane = tid & 31;

    __shared__ float s_kv[K_NB][OUTC + 1];
    __shared__ float s_q[64];
    __shared__ float s_rbf[K_NB][RBF_N];
    __shared__ float s_dirv[K_NB][3];
    __shared__ float s_l1j[K_NB][KC][3];
    __shared__ float s_inv[K_NB][KC];
    __shared__ int   s_bond[K_NB];
    __shared__ float s_attn[HEADS][K_NB];
    __shared__ float s_o0[64];
    __shared__ float s_coef[K_NB][4];
    __shared__ float s_vm[K_NB][3];
    __shared__ int   s_idx[K_NB];
    __shared__ float s_ok[K_NB];

    // ---- phase 0: q load + per-edge geometry ----
    if (tid < 64) {
        s_q[tid] = g_Qv[m * 64 + tid];
    } else if (tid < 64 + K_NB) {
        int e = tid - 64;
        int j = g_knn[m * K_NB + e];
        s_idx[e] = j;
        float rx = xyz[j * 3]     - xyz[m * 3];
        float ry = xyz[j * 3 + 1] - xyz[m * 3 + 1];
        float rz = xyz[j * 3 + 2] - xyz[m * 3 + 2];
        float d2 = rx * rx + ry * ry + rz * rz;
        float dist = sqrtf(d2 + EPSF);
        float inv_d = 1.f / dist;
        float dvx = rx * inv_d, dvy = ry * inv_d, dvz = rz * inv_d;
        s_dirv[e][0] = dvx; s_dirv[e][1] = dvy; s_dirv[e][2] = dvz;
        s_ok[e] = (j != m) ? 1.f : 0.f;
#pragma unroll
        for (int c = 0; c < KC; ++c) {
            float lx = grads[(c * M_ATOMS + j) * 3 + 0];
            float ly = grads[(c * M_ATOMS + j) * 3 + 1];
            float lz = grads[(c * M_ATOMS + j) * 3 + 2];
            s_l1j[e][c][0] = lx; s_l1j[e][c][1] = ly; s_l1j[e][c][2] = lz;
            s_inv[e][c] = lx * dvx + ly * dvy + lz * dvz;
        }
        int ri = m / A_ATOM, ai = m % A_ATOM;
        int rj = j / A_ATOM, aj = j % A_ATOM;
        int b = 0;
        if (rj == ri) b = num_bonds[(seq[ri] * A_ATOM + ai) * A_ATOM + aj];
        s_bond[e] = min(max(b, 0), MAXB);
#pragma unroll
        for (int t = 0; t < RBF_N; ++t) {
            float r = dist - 0.4f * (float)t;
            s_rbf[e][t] = __expf(-2.f * r * r);
        }
    }
    __syncthreads();

    // ---- phase 1: kv[e][d] = P[j][d] + b2 + rbf@W2 + W2[16+bond] + inv@Winv ----
    if (tid < OUTC) {
        int d = tid;
        float w2r[RBF_N];
#pragma unroll
        for (int t = 0; t < RBF_N; ++t) w2r[t] = g_W2[t * OUTC + d];
        float wb0 = g_W2[16 * OUTC + d];
        float wb1 = g_W2[17 * OUTC + d];
        float wb2 = g_W2[18 * OUTC + d];
        float wb3 = g_W2[19 * OUTC + d];
        float wb4 = g_W2[20 * OUTC + d];
        float wi0 = g_WT[96 * OUTC + d];
        float wi1 = g_WT[97 * OUTC + d];
        float wi2 = g_WT[98 * OUTC + d];
        float b2  = g_b2[d];
#pragma unroll 8
        for (int e = 0; e < K_NB; ++e) {
            int j = s_idx[e];
            float acc = b2 + g_P[j * OUTC + d];
#pragma unroll
            for (int t = 0; t < RBF_N; ++t)
                acc = fmaf(s_rbf[e][t], w2r[t], acc);
            int b = s_bond[e];
            float wb = wb0;
            if (b == 1) wb = wb1;
            else if (b == 2) wb = wb2;
            else if (b == 3) wb = wb3;
            else if (b == 4) wb = wb4;
            acc += wb;
            acc = fmaf(s_inv[e][0], wi0, acc);
            acc = fmaf(s_inv[e][1], wi1, acc);
            acc = fmaf(s_inv[e][2], wi2, acc);
            s_kv[e][d] = acc;
        }
    }
    __syncthreads();

    // ---- phase 2: logits + softmax fused (warp h handles head h) ----
    {
        int h = tid >> 5;
        if (h < HEADS) {
            float logit = -1e30f;
            if (lane < K_NB) {
                float acc = 0.f;
#pragma unroll
                for (int dh = 0; dh < DHD; ++dh)
                    acc = fmaf(s_q[h * DHD + dh], s_kv[lane][h * DHD + dh], acc);
                logit = (s_ok[lane] > 0.f) ? acc * 0.25f : -1e9f;
            }
            float mx = logit;
#pragma unroll
            for (int off = 16; off > 0; off >>= 1)
                mx = fmaxf(mx, __shfl_xor_sync(FULLW, mx, off));
            float ex = (lane < K_NB) ? __expf(logit - mx) : 0.f;
            float sm = ex;
#pragma unroll
            for (int off = 16; off > 0; off >>= 1)
                sm += __shfl_xor_sync(FULLW, sm, off);
            if (lane < K_NB) s_attn[h][lane] = ex / sm;
        }
    }
    __syncthreads();

    // ---- phase 3: o0, coef ----
    if (tid < 64) {
        int h = tid >> 4;
        float acc = 0.f;
#pragma unroll
        for (int e = 0; e < K_NB; ++e)
            acc = fmaf(s_attn[h][e], s_kv[e][64 + tid], acc);
        s_o0[tid] = acc;
    } else if (tid < 160) {
        int t = tid - 64;
        int e = t % K_NB, c = t / K_NB;   // c < 4
        float acc = 0.f;
#pragma unroll
        for (int h = 0; h < HEADS; ++h)
            acc = fmaf(s_attn[h][e], s_kv[e][128 + h * 4 + c], acc);
        s_coef[e][c] = acc;
    }
    __syncthreads();

    // ---- phase 4: out0 (state) + vmsg ----
    if (tid < 64) {
        float acc = g_S[m * 64 + tid];        // node@Wself + b0 (precomputed)
        for (int i = 0; i < 64; ++i)
            acc = fmaf(s_o0[i], Wo0[i * 64 + tid], acc);
        out[M_ATOMS * 3 + m * 64 + tid] = acc;
    } else if (tid < 64 + K_NB) {
        int e = tid - 64;
        float c0 = s_coef[e][0];
#pragma unroll
        for (int dd = 0; dd < 3; ++dd) {
            float v = c0 * s_dirv[e][dd];
#pragma unroll
            for (int c = 0; c < KC; ++c)
                v = fmaf(s_coef[e][c + 1], s_l1j[e][c][dd], v);
            s_vm[e][dd] = v;
        }
    }
    __syncthreads();

    // ---- phase 5: out1 (xyz shift) ----
    if (tid < 3) {
        float acc = 0.f;
#pragma unroll
        for (int e = 0; e < K_NB; ++e) acc += s_vm[e][tid];
        out[m * 3 + tid] = xyz[m * 3 + tid] + acc * 0.01f;
    }
}

// ---------------- launch ----------------
extern "C" void kernel_launch(void* const* d_in, const int* in_sizes, int n_in,
                              void* d_out, int out_size) {
    const int*   seq       = (const int*)d_in[0];
    const float* xyz       = (const float*)d_in[1];
    const void*  aamask    = d_in[2];
    const int*   num_bonds = (const int*)d_in[3];
    const float* state     = (const float*)d_in[4];
    const float* grads     = (const float*)d_in[5];
    int w = 6;
    if (n_in >= 16 && in_sizes[6] == 1) w = 7;
    const float* We    = (const float*)d_in[w + 0];
    const float* be    = (const float*)d_in[w + 1];
    const float* Wq    = (const float*)d_in[w + 2];
    const float* Wk    = (const float*)d_in[w + 3];
    const float* Wv0   = (const float*)d_in[w + 4];
    const float* Wv1   = (const float*)d_in[w + 5];
    const float* Wo0   = (const float*)d_in[w + 6];
    const float* Wself = (const float*)d_in[w + 7];
    const float* b0    = (const float*)d_in[w + 8];
    float* out = (float*)d_out;

    const int prep_total = KIN_DIM * OUTC + 21 * OUTC + OUTC;
    prep_kernel<<<(prep_total + 255) / 256, 256>>>(Wk, Wv0, Wv1, We, be);
    compact_kernel<<<1, 1024>>>(seq, xyz, aamask);
    pq_kernel<<<(M_ATOMS + 3) / 4, 144>>>(state, grads, Wq, Wself, b0, xyz, out);
    knn_kernel<<<(M_ATOMS + 3) / 4, 128>>>();
    attn_kernel<<<M_ATOMS, 160>>>(seq, xyz, num_bonds, grads, Wo0, out);
}